// round 9
// baseline (speedup 1.0000x reference)
#include <cuda_runtime.h>

#define BATCH   16
#define HW      1048576u
#define HW4     262144u          // HW / 4
// score s in [0.75, 4.25] -> float bits in [0x3F400000, 0x40880000]
#define B1_MIN  259072u          // 0x3F400000 >> 12
#define B1_BINS 5249             // (0x40880 - 0x3F400) + 1
#define CAND_CAP 32768
#define BT  256
#define GXH 64                   // hist blocks per batch  (stride 64*512 = 32768, 8 iters)
#define GXC 128                  // collect blocks per batch (stride 128*512 = 65536, 4 iters)
#define GXF 128                  // final blocks per batch

// All __device__ globals are zero-initialized at module load. Every kernel
// that consumes a global resets it after use, so each kernel_launch replay
// (graph) starts from a clean state without a dedicated zeroing kernel.
__device__ unsigned g_hist[BATCH][B1_BINS];
__device__ unsigned g_np[BATCH];
__device__ unsigned g_cnt[BATCH];
__device__ uint2    g_cand[BATCH][CAND_CAP];   // x = key bits, y = idx in batch
__device__ unsigned g_T[BATCH];                // threshold level-1 bin (or ~0u)
__device__ unsigned g_k1[BATCH];               // quota inside threshold bin
__device__ unsigned g_ntr[BATCH];
__device__ unsigned g_V[BATCH];                // exact cutoff key
__device__ unsigned g_ic[BATCH];               // index cutoff among key==V
__device__ double   g_loss;
__device__ unsigned g_done;                    // k_final completion counter

__device__ __forceinline__ unsigned score_key(float p, int m) {
    // bit-exact reproduction of the JAX f32 score
    float gt    = (float)m;
    float conf  = fmaxf(p, 1.0f - p);
    bool  corr  = (p > 0.5f) == (gt == 1.0f);
    bool  isc   = conf > 0.85f;
    float score = corr ? (isc ? 1.0f : 2.0f) : (isc ? 4.0f : 3.0f);
    float bonus = (conf - 0.5f) * 0.5f;      // exact in f32
    float s     = corr ? (score - bonus) : (score + bonus);
    return __float_as_uint(s);               // s > 0 => uint order == float order
}

__global__ __launch_bounds__(BT) void k_hist(const float4* __restrict__ pred,
                                             const int4* __restrict__ mask) {
    __shared__ unsigned sh[B1_BINS];
    __shared__ unsigned scnt;
    int b = blockIdx.y;
    for (int i = threadIdx.x; i < B1_BINS; i += BT) sh[i] = 0u;
    if (threadIdx.x == 0) scnt = 0u;
    __syncthreads();

    const float4* P = pred + (size_t)b * HW4;
    const int4*   M = mask + (size_t)b * HW4;
    unsigned localn = 0;
    // stride layout: block covers [bx*512, bx*512+512) per outer iter; HW4 % 32768 == 0
    for (unsigned v = blockIdx.x * (BT * 2) + threadIdx.x; v < HW4; v += BT * 2 * GXH) {
        int4   ma = M[v];
        float4 pa = P[v];
        int4   mb = M[v + BT];
        float4 pb = P[v + BT];
        if (ma.x != 2) { localn++; atomicAdd(&sh[(score_key(pa.x, ma.x) >> 12) - B1_MIN], 1u); }
        if (ma.y != 2) { localn++; atomicAdd(&sh[(score_key(pa.y, ma.y) >> 12) - B1_MIN], 1u); }
        if (ma.z != 2) { localn++; atomicAdd(&sh[(score_key(pa.z, ma.z) >> 12) - B1_MIN], 1u); }
        if (ma.w != 2) { localn++; atomicAdd(&sh[(score_key(pa.w, ma.w) >> 12) - B1_MIN], 1u); }
        if (mb.x != 2) { localn++; atomicAdd(&sh[(score_key(pb.x, mb.x) >> 12) - B1_MIN], 1u); }
        if (mb.y != 2) { localn++; atomicAdd(&sh[(score_key(pb.y, mb.y) >> 12) - B1_MIN], 1u); }
        if (mb.z != 2) { localn++; atomicAdd(&sh[(score_key(pb.z, mb.z) >> 12) - B1_MIN], 1u); }
        if (mb.w != 2) { localn++; atomicAdd(&sh[(score_key(pb.w, mb.w) >> 12) - B1_MIN], 1u); }
    }
    atomicAdd(&scnt, localn);
    __syncthreads();
    for (int i = threadIdx.x; i < B1_BINS; i += BT) {
        unsigned v = sh[i];
        if (v) atomicAdd(&g_hist[b][i], v);
    }
    if (threadIdx.x == 0) atomicAdd(&g_np[b], scnt);
}

__global__ __launch_bounds__(1024) void k_select() {
    __shared__ unsigned s[1024];
    int b = blockIdx.x;
    int t = threadIdx.x;
    const int PB = 6;                 // 1024*6 >= 5249
    unsigned local = 0;
    unsigned hv[PB];
    #pragma unroll
    for (int j = 0; j < PB; j++) {
        int pos = t * PB + j;
        hv[j] = (pos < B1_BINS) ? g_hist[b][B1_BINS - 1 - pos] : 0u;  // descending
        local += hv[j];
    }
    s[t] = local; __syncthreads();
    for (int off = 1; off < 1024; off <<= 1) {
        unsigned v = (t >= off) ? s[t - off] : 0u;
        __syncthreads();
        s[t] += v;
        __syncthreads();
    }
    unsigned before = s[t] - local;
    unsigned np  = g_np[b];
    unsigned ntr = (unsigned)(int)((float)np * 0.5f);  // matches (f32(n)*0.5).astype(i32)
    if (t == 0) g_ntr[b] = ntr;
    if (ntr == 0) {
        if (t == 0) { g_T[b] = 0xFFFFFFFFu; g_k1[b] = 0u; }
    } else if (before < ntr && before + local >= ntr) {
        unsigned acc = before;
        #pragma unroll
        for (int j = 0; j < PB; j++) {
            int pos = t * PB + j;
            if (pos >= B1_BINS) break;
            int bin = B1_BINS - 1 - pos;
            if (acc + hv[j] >= ntr) { g_T[b] = (unsigned)bin; g_k1[b] = ntr - acc; break; }
            acc += hv[j];
        }
    }
    // self-clean for next replay (all reads of g_hist/g_np above are done)
    __syncthreads();
    #pragma unroll
    for (int j = 0; j < PB; j++) {
        int pos = t * PB + j;
        if (pos < B1_BINS) g_hist[b][pos] = 0u;
    }
    if (t == 0) g_np[b] = 0u;
}

__global__ __launch_bounds__(BT) void k_collect(const float4* __restrict__ pred,
                                                const int4* __restrict__ mask) {
    int b = blockIdx.y;
    unsigned T = g_T[b];
    if (T == 0xFFFFFFFFu) return;
    const float4* P = pred + (size_t)b * HW4;
    const int4*   M = mask + (size_t)b * HW4;
    for (unsigned v = blockIdx.x * (BT * 2) + threadIdx.x; v < HW4; v += BT * 2 * GXC) {
        int4   m4[2];
        float4 p4[2];
        m4[0] = M[v];      p4[0] = P[v];
        m4[1] = M[v + BT]; p4[1] = P[v + BT];
        #pragma unroll
        for (int h = 0; h < 2; h++) {
            unsigned base = (v + h * BT) * 4u;
            #pragma unroll
            for (int k = 0; k < 4; k++) {
                int   m = (k == 0) ? m4[h].x : (k == 1) ? m4[h].y : (k == 2) ? m4[h].z : m4[h].w;
                float p = (k == 0) ? p4[h].x : (k == 1) ? p4[h].y : (k == 2) ? p4[h].z : p4[h].w;
                if (m != 2) {
                    unsigned key = score_key(p, m);
                    if (((key >> 12) - B1_MIN) == T) {
                        unsigned pos = atomicAdd(&g_cnt[b], 1u);
                        if (pos < CAND_CAP) g_cand[b][pos] = make_uint2(key, base + k);
                    }
                }
            }
        }
    }
}

__global__ __launch_bounds__(256) void k_refine() {
    __shared__ unsigned h2[4096];
    __shared__ unsigned s[256];
    __shared__ unsigned eq[2048];
    __shared__ unsigned eqc;
    __shared__ unsigned shV, shKeq, shMeq;
    int b = blockIdx.x;
    int t = threadIdx.x;
    unsigned T = g_T[b];
    if (t == 0) {
        g_ic[b] = 0xFFFFFFFFu;                 // default: take all equals
        eqc = 0u; shV = 0xFFFFFFFFu; shKeq = 0u; shMeq = 0u;
        if (T != 0xFFFFFFFFu) g_V[b] = (T + B1_MIN) << 12;  // fallback (overwritten below)
        else                  g_V[b] = 0xFFFFFFFFu;         // select nothing
    }
    __syncthreads();
    if (T == 0xFFFFFFFFu) return;            // g_cnt[b] is 0 in this case (collect skipped)

    unsigned k1 = g_k1[b];
    unsigned nc = min(g_cnt[b], (unsigned)CAND_CAP);
    for (int i = t; i < 4096; i += 256) h2[i] = 0u;
    __syncthreads();
    if (t == 0) g_cnt[b] = 0u;               // self-clean (nc already captured by all threads)
    for (unsigned i = t; i < nc; i += 256)
        atomicAdd(&h2[g_cand[b][i].x & 0xFFFu], 1u);
    __syncthreads();

    const int PB = 16;
    unsigned local = 0;
    #pragma unroll
    for (int j = 0; j < PB; j++) local += h2[4095 - (t * PB + j)];
    s[t] = local; __syncthreads();
    for (int off = 1; off < 256; off <<= 1) {
        unsigned v = (t >= off) ? s[t - off] : 0u;
        __syncthreads();
        s[t] += v;
        __syncthreads();
    }
    unsigned before = s[t] - local;
    if (before < k1 && before + local >= k1) {
        unsigned acc = before;
        for (int j = 0; j < PB; j++) {
            int v = 4095 - (t * PB + j);
            unsigned h = h2[v];
            if (acc + h >= k1) {
                unsigned V = ((T + B1_MIN) << 12) | (unsigned)v;
                shV = V; shKeq = k1 - acc; shMeq = h;
                g_V[b] = V;
                break;
            }
            acc += h;
        }
    }
    __syncthreads();
    unsigned V = shV, keq = shKeq, meq = shMeq;
    if (V == 0xFFFFFFFFu) return;            // degenerate fallback only
    if (keq == meq) return;                  // all equal-key elements selected

    for (unsigned i = t; i < nc; i += 256) {
        if (g_cand[b][i].x == V) {
            unsigned p = atomicAdd(&eqc, 1u);
            if (p < 2048u) eq[p] = g_cand[b][i].y;
        }
    }
    __syncthreads();
    unsigned m = min(eqc, 2048u);
    if (keq < m) {
        // find index with rank == keq (indices are distinct)
        for (unsigned i = t; i < m; i += 256) {
            unsigned x = eq[i], r = 0;
            for (unsigned j = 0; j < m; j++) r += (eq[j] < x) ? 1u : 0u;
            if (r == keq) g_ic[b] = x;       // select idx < g_ic
        }
    }
}

__global__ __launch_bounds__(BT) void k_final(const float4* __restrict__ pred,
                                              const int4* __restrict__ mask,
                                              float* __restrict__ out) {
    int b = blockIdx.y;
    unsigned V  = g_V[b];
    unsigned ic = g_ic[b];
    const float4* P = pred + (size_t)b * HW4;
    const int4*   M = mask + (size_t)b * HW4;
    // out+1 is only 4B-aligned -> scalar streaming stores for the masks
    float* outT = out + 1 + (size_t)b * HW;
    float* outH = out + 1 + (size_t)BATCH * HW + (size_t)b * HW;

    double acc = 0.0;
    for (unsigned v = blockIdx.x * (BT * 2) + threadIdx.x; v < HW4; v += BT * 2 * GXF) {
        int4   m4[2];
        float4 p4[2];
        m4[0] = M[v];      p4[0] = P[v];
        m4[1] = M[v + BT]; p4[1] = P[v + BT];
        #pragma unroll
        for (int h = 0; h < 2; h++) {
            unsigned base = (v + h * BT) * 4u;
            #pragma unroll
            for (int k = 0; k < 4; k++) {
                int   m = (k == 0) ? m4[h].x : (k == 1) ? m4[h].y : (k == 2) ? m4[h].z : m4[h].w;
                float p = (k == 0) ? p4[h].x : (k == 1) ? p4[h].y : (k == 2) ? p4[h].z : p4[h].w;
                bool ann = (m != 2);
                bool train = false;
                if (ann) {
                    unsigned key = score_key(p, m);
                    train = (key > V) || (key == V && (base + k) < ic);
                }
                bool hold = ann && !train;
                __stcs(&outT[base + k], train ? 1.0f : 0.0f);
                __stcs(&outH[base + k], hold  ? 1.0f : 0.0f);
                if (train) {
                    float pc = fminf(fmaxf(p, 1e-7f), 1.0f - 1e-7f);
                    float bce = (m == 1) ? -logf(pc) : -logf(1.0f - pc);
                    acc += (double)bce;
                }
            }
        }
    }
    // warp + block reduce, one double atomic per block
    #pragma unroll
    for (int off = 16; off; off >>= 1)
        acc += __shfl_down_sync(0xFFFFFFFFu, acc, off);
    __shared__ double w[BT / 32];
    __shared__ bool last;
    int lane = threadIdx.x & 31, warp = threadIdx.x >> 5;
    if (lane == 0) w[warp] = acc;
    __syncthreads();
    if (threadIdx.x == 0) {
        double s2 = 0.0;
        #pragma unroll
        for (int i = 0; i < BT / 32; i++) s2 += w[i];
        atomicAdd(&g_loss, s2);
        __threadfence();
        unsigned prev = atomicAdd(&g_done, 1u);
        last = (prev == GXF * BATCH - 1u);
    }
    __syncthreads();
    if (last && threadIdx.x == 0) {
        // all blocks' g_loss contributions are visible (fence + atomic chain)
        unsigned tot = 0;
        #pragma unroll
        for (int i = 0; i < BATCH; i++) tot += g_ntr[i];
        out[0] = (float)g_loss / ((float)tot + 1e-7f);
        g_loss = 0.0;          // self-clean for next replay
        g_done = 0u;
    }
}

extern "C" void kernel_launch(void* const* d_in, const int* in_sizes, int n_in,
                              void* d_out, int out_size) {
    const float4* pred = (const float4*)d_in[0];
    const int4*   mask = (const int4*)d_in[1];
    float* out = (float*)d_out;
    k_hist<<<dim3(GXH, BATCH), BT>>>(pred, mask);
    k_select<<<BATCH, 1024>>>();
    k_collect<<<dim3(GXC, BATCH), BT>>>(pred, mask);
    k_refine<<<BATCH, 256>>>();
    k_final<<<dim3(GXF, BATCH), BT>>>(pred, mask, out);
}